// round 16
// baseline (speedup 1.0000x reference)
#include <cuda_runtime.h>
#include <cuda_bf16.h>
#include <cstdint>
#include <math.h>

#define H_DIM 768
#define S_LEN 512
#define B_SZ 128
#define F4_ROW 192
#define CHUNKS 6
#define THREADS 512                 // 16 warps; 2 blocks/SM -> 32 warps/SM
#define BLOCKS 256                  // half batch per block; single wave (<=304)
#define STG_ROWS 16
#define STG_B (STG_ROWS * H_DIM * 4)   // 49152
#define NSTAGES 16                  // 16 x 16 rows = 256 rows per block
#define WS_OFF 0                    // 9216 B
#define FEATS_OFF 9216              // 3072 B
#define MBAR_OFF 12288              // full[2]@+0, empty[2]@+16
#define STAGES_OFF 12544
#define DYN_SMEM (STAGES_OFF + 2 * STG_B)   // 110848
#define LN2F 0.6931471805599453f
#define FULLM 0xffffffffu

__device__ float g_sm_[2 * B_SZ][9];
__device__ float g_sls[2 * B_SZ];
__device__ float g_sg[2 * B_SZ];
__device__ float g_part[B_SZ];
__device__ unsigned int g_cnt[B_SZ];   // zero-init; combiner resets
__device__ unsigned int g_done;        // zero-init; finalizer resets

__device__ __forceinline__ uint32_t smem_u32(const void* p) {
    uint32_t a;
    asm("{ .reg .u64 t; cvta.to.shared.u64 t, %1; cvt.u32.u64 %0, t; }" : "=r"(a) : "l"(p));
    return a;
}
__device__ __forceinline__ void mbar_init(uint32_t mb, uint32_t cnt) {
    asm volatile("mbarrier.init.shared.b64 [%0], %1;" :: "r"(mb), "r"(cnt) : "memory");
}
__device__ __forceinline__ void mbar_expect_tx(uint32_t mb, uint32_t bytes) {
    asm volatile("mbarrier.arrive.expect_tx.shared.b64 _, [%0], %1;" :: "r"(mb), "r"(bytes) : "memory");
}
__device__ __forceinline__ void mbar_arrive(uint32_t mb) {
    asm volatile("mbarrier.arrive.shared.b64 _, [%0];" :: "r"(mb) : "memory");
}
__device__ __forceinline__ void mbar_wait(uint32_t mb, uint32_t parity) {
    asm volatile(
        "{\n\t.reg .pred P;\n\t"
        "W_%=:\n\t"
        "mbarrier.try_wait.parity.acquire.cta.shared::cta.b64 P, [%0], %1, 0x989680;\n\t"
        "@P bra.uni D_%=;\n\t"
        "bra.uni W_%=;\n\t"
        "D_%=:\n\t}"
        :: "r"(mb), "r"(parity) : "memory");
}
__device__ __forceinline__ void tma_bulk_1d(uint32_t dst, const void* src, uint32_t bytes, uint32_t mb) {
    asm volatile(
        "cp.async.bulk.shared::cluster.global.mbarrier::complete_tx::bytes [%0], [%1], %2, [%3];"
        :: "r"(dst), "l"(src), "r"(bytes), "r"(mb) : "memory");
}

__device__ __forceinline__ void renorm9(float a[9], float& ls) {
    float m = a[0];
    #pragma unroll
    for (int e = 1; e < 9; e++) m = fmaxf(m, a[e]);
    int eb = (__float_as_int(m) >> 23) - 127;
    float s = __int_as_float((127 - eb) << 23);
    #pragma unroll
    for (int e = 0; e < 9; e++) a[e] *= s;
    ls += (float)eb * LN2F;
}
__device__ __forceinline__ void mm3(const float a[9], const float b[9], float n[9]) {
    #pragma unroll
    for (int i = 0; i < 3; i++) {
        n[i*3+0] = fmaf(a[i*3], b[0], fmaf(a[i*3+1], b[3], a[i*3+2] * b[6]));
        n[i*3+1] = fmaf(a[i*3], b[1], fmaf(a[i*3+1], b[4], a[i*3+2] * b[7]));
        n[i*3+2] = fmaf(a[i*3], b[2], fmaf(a[i*3+1], b[5], a[i*3+2] * b[8]));
    }
}

__global__ __launch_bounds__(THREADS, 2) void fused_kernel(
    const float* __restrict__ x, const void* __restrict__ yraw,
    const float* __restrict__ W, const float* __restrict__ bias,
    const float* __restrict__ trans, const float* __restrict__ start_t,
    const float* __restrict__ stop_t, float* __restrict__ out, int out_size)
{
    extern __shared__ char dyn[];
    float4* ws   = reinterpret_cast<float4*>(dyn + WS_OFF);
    float* feats = reinterpret_cast<float*>(dyn + FEATS_OFF);
    uint32_t smb = smem_u32(dyn);

    __shared__ float bs[3], tr_sm[9], etr_sm[9], st_sm[3], sp_sm[3];
    __shared__ float wm[8][9], wls[8], wgold[8];
    __shared__ int s_flag;

    int tid  = threadIdx.x;
    int lane = tid & 31;
    int w    = tid >> 5;

    for (int i = tid; i < 3 * F4_ROW; i += THREADS)
        ws[i] = reinterpret_cast<const float4*>(W)[i];
    if (tid < 9) { float t = trans[tid]; tr_sm[tid] = t; etr_sm[tid] = __expf(t); }
    if (tid < 3) { bs[tid] = bias[tid]; st_sm[tid] = start_t[tid]; sp_sm[tid] = stop_t[tid]; }
    if (tid == 0) {
        mbar_init(smb + MBAR_OFF + 0, 1);        // full[0]: tx-based
        mbar_init(smb + MBAR_OFF + 8, 1);        // full[1]
        mbar_init(smb + MBAR_OFF + 16, 256);     // empty[0]: group A threads
        mbar_init(smb + MBAR_OFF + 24, 256);     // empty[1]: group B threads
    }
    __syncthreads();

    // ---------------- pred: TMA-fed double-buffer, 2 groups x 8 warps ----------------
    int group = w >> 3;                 // 0: warps 0-7 (even stages/slot0), 1: warps 8-15
    int wl    = w & 7;
    const char* xsrc = (const char*)x + (size_t)blockIdx.x * 256 * (H_DIM * 4);

    int issued = 0;                     // meaningful in tid 0 only
    #pragma unroll 1
    for (int it = 0; it < 8; it++) {
        int s = 2 * it + group;

        if (tid == 0) {
            int sA = 2 * it;
            while (issued < NSTAGES && issued <= sA + 1) {
                int slot = issued & 1;
                if (issued >= 2)        // wait consumer of stage issued-2 (same slot)
                    mbar_wait(smb + MBAR_OFF + 16 + slot * 8, (unsigned)(((issued >> 1) - 1) & 1));
                uint32_t mb = smb + MBAR_OFF + slot * 8;
                mbar_expect_tx(mb, STG_B);
                tma_bulk_1d(smb + STAGES_OFF + slot * STG_B,
                            xsrc + (size_t)issued * STG_B, STG_B, mb);
                issued++;
            }
        }

        // all threads of this group: wait stage full
        int slot = s & 1;               // == group
        mbar_wait(smb + MBAR_OFF + slot * 8, (unsigned)((s >> 1) & 1));

        const float4* stage = reinterpret_cast<const float4*>(dyn + STAGES_OFF + slot * STG_B);
        int r0 = wl * 2;                // 2 rows per warp within the 16-row stage

        float a00=0.f,a01=0.f,a02=0.f, a10=0.f,a11=0.f,a12=0.f;
        #pragma unroll
        for (int c = 0; c < CHUNKS; c++) {
            float4 x0 = stage[(size_t)r0 * F4_ROW + c * 32 + lane];
            float4 x1 = stage[(size_t)(r0 + 1) * F4_ROW + c * 32 + lane];
            float4 w0 = ws[c * 32 + lane];
            float4 w1 = ws[192 + c * 32 + lane];
            float4 w2 = ws[384 + c * 32 + lane];
            a00 = fmaf(x0.x, w0.x, fmaf(x0.y, w0.y, fmaf(x0.z, w0.z, fmaf(x0.w, w0.w, a00))));
            a01 = fmaf(x0.x, w1.x, fmaf(x0.y, w1.y, fmaf(x0.z, w1.z, fmaf(x0.w, w1.w, a01))));
            a02 = fmaf(x0.x, w2.x, fmaf(x0.y, w2.y, fmaf(x0.z, w2.z, fmaf(x0.w, w2.w, a02))));
            a10 = fmaf(x1.x, w0.x, fmaf(x1.y, w0.y, fmaf(x1.z, w0.z, fmaf(x1.w, w0.w, a10))));
            a11 = fmaf(x1.x, w1.x, fmaf(x1.y, w1.y, fmaf(x1.z, w1.z, fmaf(x1.w, w1.w, a11))));
            a12 = fmaf(x1.x, w2.x, fmaf(x1.y, w2.y, fmaf(x1.z, w2.z, fmaf(x1.w, w2.w, a12))));
        }
        #pragma unroll
        for (int off = 16; off; off >>= 1) {
            a00 += __shfl_xor_sync(FULLM, a00, off); a01 += __shfl_xor_sync(FULLM, a01, off);
            a02 += __shfl_xor_sync(FULLM, a02, off); a10 += __shfl_xor_sync(FULLM, a10, off);
            a11 += __shfl_xor_sync(FULLM, a11, off); a12 += __shfl_xor_sync(FULLM, a12, off);
        }
        if (lane < 2) {
            float v0 = (lane == 0 ? a00 : a10) + bs[0];
            float v1 = (lane == 0 ? a01 : a11) + bs[1];
            float v2 = (lane == 0 ? a02 : a12) + bs[2];
            int tl = s * STG_ROWS + r0 + lane;             // local timestep 0..255
            int row = blockIdx.x * 256 + tl;
            float* o = out + (size_t)row * 3;
            o[0] = v0; o[1] = v1; o[2] = v2;
            feats[tl * 3 + 0] = v0;
            feats[tl * 3 + 1] = v1;
            feats[tl * 3 + 2] = v2;
        }
        mbar_arrive(smb + MBAR_OFF + 16 + slot * 8);       // stage consumed
    }
    __syncthreads();

    // ---------------- CRF partial for this half-batch (256 leaves) ----------------
    int b    = blockIdx.x >> 1;
    int half = blockIdx.x & 1;

    if (w < 8) {
        // warps 0-7: chain product, 1 timestep per lane
        int tl = w * 32 + lane;
        int tb = half * 256 + tl;
        float f0 = feats[tl*3], f1 = feats[tl*3+1], f2 = feats[tl*3+2];
        if (tb == 0) { f0 += st_sm[0]; f1 += st_sm[1]; f2 += st_sm[2]; }
        float c  = fmaxf(f0, fmaxf(f1, f2));
        float e0 = __expf(f0 - c), e1 = __expf(f1 - c), e2 = __expf(f2 - c);
        float a[9]; float ls = c;
        if (tb == 0) {
            a[0]=e0; a[1]=e1; a[2]=e2; a[3]=e0; a[4]=e1; a[5]=e2; a[6]=e0; a[7]=e1; a[8]=e2;
        } else {
            #pragma unroll
            for (int i = 0; i < 3; i++) {
                a[i*3+0] = etr_sm[i*3+0] * e0;
                a[i*3+1] = etr_sm[i*3+1] * e1;
                a[i*3+2] = etr_sm[i*3+2] * e2;
            }
        }
        #pragma unroll
        for (int off = 1; off < 32; off <<= 1) {
            float bm[9];
            #pragma unroll
            for (int e = 0; e < 9; e++) bm[e] = __shfl_down_sync(FULLM, a[e], off);
            float lsb = __shfl_down_sync(FULLM, ls, off);
            if ((lane & (2 * off - 1)) == 0) {
                float n[9];
                mm3(a, bm, n);
                #pragma unroll
                for (int e = 0; e < 9; e++) a[e] = n[e];
                ls += lsb;
                renorm9(a, ls);
            }
        }
        if (lane == 0) {
            #pragma unroll
            for (int e = 0; e < 9; e++) wm[w][e] = a[e];
            wls[w] = ls;
        }
    } else {
        // warps 8-15: gold-path partial, 1 timestep per lane
        int tl = (w - 8) * 32 + lane;
        int tb = half * 256 + tl;
        // y dtype sniff (values 0..2; LE int64 -> odd 32-bit words zero)
        const int* yw = (const int*)yraw;
        int oddw = (lane < 16) ? yw[2 * lane + 1] : 0;
        int stride = (__ballot_sync(FULLM, oddw != 0) == 0u) ? 2 : 1;
        const int* yb = yw + (size_t)b * S_LEN * stride;

        int tg = yb[tb * stride];
        float g = feats[tl * 3 + tg];
        if (tb > 0) { int tp = yb[(tb - 1) * stride]; g += tr_sm[tp * 3 + tg]; }
        else         g += st_sm[tg];
        if (tb == S_LEN - 1) g += sp_sm[tg];
        #pragma unroll
        for (int off = 16; off; off >>= 1) g += __shfl_xor_sync(FULLM, g, off);
        if (lane == 0) wgold[w - 8] = g;
    }
    __syncthreads();

    if (tid == 0) {
        float p[9], n[9];
        #pragma unroll
        for (int e = 0; e < 9; e++) p[e] = wm[0][e];
        float ls = wls[0];
        float gold = wgold[0];
        #pragma unroll
        for (int j = 1; j < 8; j++) {
            mm3(p, wm[j], n);
            #pragma unroll
            for (int e = 0; e < 9; e++) p[e] = n[e];
            ls += wls[j];
            renorm9(p, ls);
            gold += wgold[j];
        }
        #pragma unroll
        for (int e = 0; e < 9; e++) g_sm_[blockIdx.x][e] = p[e];
        g_sls[blockIdx.x] = ls;
        g_sg[blockIdx.x]  = gold;
        __threadfence();
        s_flag = (atomicAdd(&g_cnt[b], 1) == 1);   // 2 producers per batch
    }
    __syncthreads();
    if (!s_flag) return;

    // ---------------- batch combine (2 halves) + finalize ----------------
    if (tid == 0) {
        __threadfence();
        int base = b * 2;
        float p[9], n[9], q9[9];
        #pragma unroll
        for (int e = 0; e < 9; e++) p[e] = __ldcg(&g_sm_[base][e]);
        #pragma unroll
        for (int e = 0; e < 9; e++) q9[e] = __ldcg(&g_sm_[base + 1][e]);
        mm3(p, q9, n);
        float ls = __ldcg(&g_sls[base]) + __ldcg(&g_sls[base + 1]);
        renorm9(n, ls);
        float gold = __ldcg(&g_sg[base]) + __ldcg(&g_sg[base + 1]);
        float z = n[0] * __expf(sp_sm[0]) + n[1] * __expf(sp_sm[1]) + n[2] * __expf(sp_sm[2]);
        g_part[b] = gold - (ls + __logf(z));
        g_cnt[b] = 0;
        __threadfence();
        s_flag = ((int)atomicAdd(&g_done, 1) == B_SZ - 1);
    }
    __syncthreads();

    if (s_flag && w == 0) {
        __threadfence();
        float s = __ldcg(&g_part[lane])      + __ldcg(&g_part[lane + 32])
                + __ldcg(&g_part[lane + 64]) + __ldcg(&g_part[lane + 96]);
        #pragma unroll
        for (int off = 16; off; off >>= 1) s += __shfl_xor_sync(FULLM, s, off);
        if (lane == 0) {
            out[out_size - 1] = -s / (float)B_SZ;
            g_done = 0;
        }
    }
}

// ---------------- launch ----------------
extern "C" void kernel_launch(void* const* d_in, const int* in_sizes, int n_in,
                              void* d_out, int out_size)
{
    const float* x     = (const float*)d_in[0];
    const void*  y     = d_in[1];
    const float* W     = (const float*)d_in[2];
    const float* bias  = (const float*)d_in[3];
    const float* trans = (const float*)d_in[4];
    const float* st    = (const float*)d_in[5];
    const float* sp    = (const float*)d_in[6];
    float* out = (float*)d_out;

    static int attr_done = 0;
    if (!attr_done) {
        cudaFuncSetAttribute(fused_kernel,
                             cudaFuncAttributeMaxDynamicSharedMemorySize, DYN_SMEM);
        attr_done = 1;
    }

    fused_kernel<<<BLOCKS, THREADS, DYN_SMEM>>>(x, y, W, bias, trans, st, sp,
                                                out, out_size);
}

// round 17
// speedup vs baseline: 1.0569x; 1.0569x over previous
#include <cuda_runtime.h>
#include <cuda_bf16.h>
#include <math.h>

#define H_DIM 768
#define S_LEN 512
#define B_SZ 128
#define F4_PER_ROW (H_DIM / 4)      // 192
#define CHUNKS (H_DIM / 128)        // 6
#define RQ 4
#define QPW 2                       // 8 rows/warp -> 64 rows/block (R4 shape)
#define THREADS 256
#define BLOCKS 1024                 // 1.68 waves: oversubscription load-balances
#define LN2F 0.6931471805599453f
#define FULLM 0xffffffffu

// Per-block CRF partials (block = eighth of a batch)
__device__ float g_sm_[BLOCKS][9];
__device__ float g_sls[BLOCKS];
__device__ float g_sg[BLOCKS];
__device__ float g_part[B_SZ];
__device__ unsigned int g_cnt[B_SZ];   // zero-init; combiner resets its slot
__device__ unsigned int g_done;        // zero-init; finalizer resets

__device__ __forceinline__ void renorm9(float a[9], float& ls) {
    float m = a[0];
    #pragma unroll
    for (int e = 1; e < 9; e++) m = fmaxf(m, a[e]);
    int eb = (__float_as_int(m) >> 23) - 127;
    float s = __int_as_float((127 - eb) << 23);   // exact 2^-eb
    #pragma unroll
    for (int e = 0; e < 9; e++) a[e] *= s;
    ls += (float)eb * LN2F;
}

__device__ __forceinline__ void mm3(const float a[9], const float b[9], float n[9]) {
    #pragma unroll
    for (int i = 0; i < 3; i++) {
        n[i*3+0] = fmaf(a[i*3], b[0], fmaf(a[i*3+1], b[3], a[i*3+2] * b[6]));
        n[i*3+1] = fmaf(a[i*3], b[1], fmaf(a[i*3+1], b[4], a[i*3+2] * b[7]));
        n[i*3+2] = fmaf(a[i*3], b[2], fmaf(a[i*3+1], b[5], a[i*3+2] * b[8]));
    }
}

__global__ __launch_bounds__(THREADS, 4) void fused_kernel(
    const float* __restrict__ x, const void* __restrict__ yraw,
    const float* __restrict__ W, const float* __restrict__ bias,
    const float* __restrict__ trans, const float* __restrict__ start_t,
    const float* __restrict__ stop_t, float* __restrict__ out,
    int nrows, int out_size)
{
    __shared__ float4 ws[3 * F4_PER_ROW];   // 9 KB
    __shared__ float bs[3];
    __shared__ float feats_sm[64 * 3];      // this block's 64 rows
    __shared__ float tr_sm[9], etr_sm[9], st_sm[3], sp_sm[3];
    __shared__ float wm[2][9], wls[2], wgold[2];
    __shared__ int s_flag;

    int tid  = threadIdx.x;
    int lane = tid & 31;
    int w    = tid >> 5;

    for (int i = tid; i < 3 * F4_PER_ROW; i += THREADS)
        ws[i] = reinterpret_cast<const float4*>(W)[i];
    if (tid < 9) { float t = trans[tid]; tr_sm[tid] = t; etr_sm[tid] = __expf(t); }
    if (tid < 3) { bs[tid] = bias[tid]; st_sm[tid] = start_t[tid]; sp_sm[tid] = stop_t[tid]; }
    __syncthreads();

    // ---------------- pred: 64 rows (R4-proven shape: 8 warps x 2 quads x 4 rows) ----------------
    int gw = blockIdx.x * 8 + w;
    #pragma unroll
    for (int q = 0; q < QPW; q++) {
        int row0 = gw * (QPW * RQ) + q * RQ;
        if (row0 >= nrows) break;
        const float4* xr = reinterpret_cast<const float4*>(x)
                           + (size_t)row0 * F4_PER_ROW + lane;

        float a[RQ][3];
        #pragma unroll
        for (int r = 0; r < RQ; r++) { a[r][0] = 0.f; a[r][1] = 0.f; a[r][2] = 0.f; }

        #pragma unroll
        for (int i = 0; i < CHUNKS; i++) {
            float4 xv[RQ];
            #pragma unroll
            for (int r = 0; r < RQ; r++)
                xv[r] = __ldcs(&xr[(size_t)r * F4_PER_ROW + i * 32]);
            float4 w0 = ws[i * 32 + lane];
            float4 w1 = ws[192 + i * 32 + lane];
            float4 w2 = ws[384 + i * 32 + lane];
            #pragma unroll
            for (int r = 0; r < RQ; r++) {
                float4 t = xv[r];
                a[r][0] = fmaf(t.x, w0.x, fmaf(t.y, w0.y, fmaf(t.z, w0.z, fmaf(t.w, w0.w, a[r][0]))));
                a[r][1] = fmaf(t.x, w1.x, fmaf(t.y, w1.y, fmaf(t.z, w1.z, fmaf(t.w, w1.w, a[r][1]))));
                a[r][2] = fmaf(t.x, w2.x, fmaf(t.y, w2.y, fmaf(t.z, w2.z, fmaf(t.w, w2.w, a[r][2]))));
            }
        }

        #pragma unroll
        for (int off = 16; off; off >>= 1) {
            #pragma unroll
            for (int r = 0; r < RQ; r++) {
                a[r][0] += __shfl_xor_sync(FULLM, a[r][0], off);
                a[r][1] += __shfl_xor_sync(FULLM, a[r][1], off);
                a[r][2] += __shfl_xor_sync(FULLM, a[r][2], off);
            }
        }
        if (lane < RQ) {
            float v0 = a[lane][0] + bs[0];
            float v1 = a[lane][1] + bs[1];
            float v2 = a[lane][2] + bs[2];
            float* o = out + (size_t)(row0 + lane) * 3;
            o[0] = v0; o[1] = v1; o[2] = v2;
            int tl = w * 8 + q * 4 + lane;        // local timestep 0..63
            feats_sm[tl * 3 + 0] = v0;
            feats_sm[tl * 3 + 1] = v1;
            feats_sm[tl * 3 + 2] = v2;
        }
    }
    __syncthreads();

    // ---------------- per-block CRF partial (overlaps other blocks' memory phase) ----------------
    int b       = blockIdx.x >> 3;           // 8 blocks per batch
    int tb_base = (blockIdx.x & 7) * 64;     // first timestep in batch

    if (w < 2) {
        // warps 0-1: chain product of 32 leaves each (1 timestep per lane)
        int tl = w * 32 + lane;
        int tb = tb_base + tl;
        float f0 = feats_sm[tl*3], f1 = feats_sm[tl*3+1], f2 = feats_sm[tl*3+2];
        if (tb == 0) { f0 += st_sm[0]; f1 += st_sm[1]; f2 += st_sm[2]; }
        float c  = fmaxf(f0, fmaxf(f1, f2));
        float e0 = __expf(f0 - c), e1 = __expf(f1 - c), e2 = __expf(f2 - c);
        float a[9]; float ls = c;
        if (tb == 0) {                        // rank-1 a0 leaf
            a[0]=e0; a[1]=e1; a[2]=e2; a[3]=e0; a[4]=e1; a[5]=e2; a[6]=e0; a[7]=e1; a[8]=e2;
        } else {
            #pragma unroll
            for (int i = 0; i < 3; i++) {
                a[i*3+0] = etr_sm[i*3+0] * e0;
                a[i*3+1] = etr_sm[i*3+1] * e1;
                a[i*3+2] = etr_sm[i*3+2] * e2;
            }
        }
        // ordered shuffle tree within warp
        #pragma unroll
        for (int off = 1; off < 32; off <<= 1) {
            float bm[9];
            #pragma unroll
            for (int e = 0; e < 9; e++) bm[e] = __shfl_down_sync(FULLM, a[e], off);
            float lsb = __shfl_down_sync(FULLM, ls, off);
            if ((lane & (2 * off - 1)) == 0) {
                float n[9];
                mm3(a, bm, n);
                #pragma unroll
                for (int e = 0; e < 9; e++) a[e] = n[e];
                ls += lsb;
                renorm9(a, ls);
            }
        }
        if (lane == 0) {
            #pragma unroll
            for (int e = 0; e < 9; e++) wm[w][e] = a[e];
            wls[w] = ls;
        }
    } else if (w < 4) {
        // warps 2-3: gold-path partial (1 timestep per lane)
        int tl = (w - 2) * 32 + lane;
        int tb = tb_base + tl;
        // y dtype sniff (values 0..2; LE int64 -> odd 32-bit words zero)
        const int* yw = (const int*)yraw;
        int oddw = (lane < 16) ? yw[2 * lane + 1] : 0;
        int stride = (__ballot_sync(FULLM, oddw != 0) == 0u) ? 2 : 1;
        const int* yb = yw + (size_t)b * S_LEN * stride;

        int tg = yb[tb * stride];
        float g = feats_sm[tl * 3 + tg];
        if (tb > 0) { int tp = yb[(tb - 1) * stride]; g += tr_sm[tp * 3 + tg]; }
        else         g += st_sm[tg];
        if (tb == S_LEN - 1) g += sp_sm[tg];
        #pragma unroll
        for (int off = 16; off; off >>= 1) g += __shfl_xor_sync(FULLM, g, off);
        if (lane == 0) wgold[w - 2] = g;
    }
    __syncthreads();

    if (tid == 0) {
        float p[9];
        mm3(wm[0], wm[1], p);
        float ls = wls[0] + wls[1];
        renorm9(p, ls);
        #pragma unroll
        for (int e = 0; e < 9; e++) g_sm_[blockIdx.x][e] = p[e];
        g_sls[blockIdx.x] = ls;
        g_sg[blockIdx.x]  = wgold[0] + wgold[1];
        __threadfence();
        s_flag = (atomicAdd(&g_cnt[b], 1) == 7);
    }
    __syncthreads();
    if (!s_flag) return;

    // ---------------- batch combine: ordered product of 8 block partials ----------------
    if (tid == 0) {
        __threadfence();                     // acquire other producers' scratch
        int base = b * 8;
        float p[9], n[9], q9[9];
        #pragma unroll
        for (int e = 0; e < 9; e++) p[e] = __ldcg(&g_sm_[base][e]);
        float ls   = __ldcg(&g_sls[base]);
        float gold = __ldcg(&g_sg[base]);
        #pragma unroll
        for (int j = 1; j < 8; j++) {
            #pragma unroll
            for (int e = 0; e < 9; e++) q9[e] = __ldcg(&g_sm_[base + j][e]);
            mm3(p, q9, n);
            #pragma unroll
            for (int e = 0; e < 9; e++) p[e] = n[e];
            ls += __ldcg(&g_sls[base + j]);
            renorm9(p, ls);
            gold += __ldcg(&g_sg[base + j]);
        }
        float z = p[0] * __expf(sp_sm[0]) + p[1] * __expf(sp_sm[1]) + p[2] * __expf(sp_sm[2]);
        g_part[b] = gold - (ls + __logf(z));
        g_cnt[b] = 0;                        // self-reset for next graph replay
        __threadfence();
        s_flag = ((int)atomicAdd(&g_done, 1) == B_SZ - 1);
    }
    __syncthreads();

    // ---------------- finalize: 128th batch-completer reduces all partials ----------------
    if (s_flag && w == 0) {
        __threadfence();
        float s = __ldcg(&g_part[lane])      + __ldcg(&g_part[lane + 32])
                + __ldcg(&g_part[lane + 64]) + __ldcg(&g_part[lane + 96]);
        #pragma unroll
        for (int off = 16; off; off >>= 1) s += __shfl_xor_sync(FULLM, s, off);
        if (lane == 0) {
            out[out_size - 1] = -s / (float)B_SZ;
            g_done = 0;                      // self-reset for next graph replay
        }
    }
}

// ---------------- launch ----------------
extern "C" void kernel_launch(void* const* d_in, const int* in_sizes, int n_in,
                              void* d_out, int out_size)
{
    const float* x     = (const float*)d_in[0];
    const void*  y     = d_in[1];
    const float* W     = (const float*)d_in[2];
    const float* bias  = (const float*)d_in[3];
    const float* trans = (const float*)d_in[4];
    const float* st    = (const float*)d_in[5];
    const float* sp    = (const float*)d_in[6];
    float* out = (float*)d_out;

    int nrows = in_sizes[0] / H_DIM;    // 65536

    fused_kernel<<<BLOCKS, THREADS>>>(x, y, W, bias, trans, st, sp,
                                      out, nrows, out_size);
}